// round 15
// baseline (speedup 1.0000x reference)
#include <cuda_runtime.h>
#include <cuda_fp16.h>
#include <math.h>

#define HH 1024
#define WW 1024
#define BBATCH 8
#define PLANE (HH*WW)          // 1<<20
#define NPIX (BBATCH*PLANE)    // 8<<20

// fp16 intermediates: max/min pooling is exact selection on quantized values
// (quantization is monotone, so it commutes with max/min).
__device__ __align__(16) __half g_E[NPIX];   // edge_soft
__device__ __align__(16) __half g_A[NPIX];   // hmax out, then closed
__device__ __align__(16) __half g_B2[NPIX];  // hmin(dilated)
__device__ float  g_acc[3];    // mask_sum, chroma_sum, hue_sum

__device__ __forceinline__ float4 ld4f(const float* p){ return *reinterpret_cast<const float4*>(p); }

template<bool M>
__device__ __forceinline__ float rop(float a, float b){ return M ? fmaxf(a,b) : fminf(a,b); }

__device__ __forceinline__ float2 h2f(unsigned u){ return __half22float2(*reinterpret_cast<const __half2*>(&u)); }

// Load 14-half window a[0..13] = cols x0-5..x0+8 (clamped) from a half row.
// Alignment-safe for x0 multiple of 4 halves. Works for global or shared ptrs.
__device__ __forceinline__ void hwin14(const __half* __restrict__ p, int x0, float* a)
{
    if (x0 >= 8 && x0 <= WW-12) {
        unsigned u0 = *reinterpret_cast<const unsigned*>(p + x0 - 6);
        uint2 v0 = *reinterpret_cast<const uint2*>(p + x0 - 4);
        uint2 v1 = *reinterpret_cast<const uint2*>(p + x0);
        uint2 v2 = *reinterpret_cast<const uint2*>(p + x0 + 4);
        unsigned u1 = *reinterpret_cast<const unsigned*>(p + x0 + 8);
        float2 q;
        q = h2f(u0);   a[0] = q.y;
        q = h2f(v0.x); a[1] = q.x; a[2] = q.y;
        q = h2f(v0.y); a[3] = q.x; a[4] = q.y;
        q = h2f(v1.x); a[5] = q.x; a[6] = q.y;
        q = h2f(v1.y); a[7] = q.x; a[8] = q.y;
        q = h2f(v2.x); a[9] = q.x; a[10]= q.y;
        q = h2f(v2.y); a[11]= q.x; a[12]= q.y;
        q = h2f(u1);   a[13]= q.x;
    } else {
        #pragma unroll
        for (int i=0;i<14;i++){
            int xx = x0-5+i; xx = xx < 0 ? 0 : (xx > WW-1 ? WW-1 : xx);
            a[i] = __half2float(p[xx]);
        }
    }
}

// Shared-prefix 11-tap tree over a[0..13] -> 4 outputs (cols x0..x0+3)
template<bool M>
__device__ __forceinline__ void htree11(const float* a, float* o)
{
    float C = a[3];
    #pragma unroll
    for (int i=4;i<=10;i++) C = rop<M>(C, a[i]);
    float t12 = rop<M>(a[1],  a[2]);
    float t23 = rop<M>(a[11], a[12]);
    o[0] = rop<M>(C, rop<M>(a[0], t12));
    o[1] = rop<M>(C, rop<M>(t12,  a[11]));
    o[2] = rop<M>(rop<M>(C, a[2]),  t23);
    o[3] = rop<M>(rop<M>(C, a[13]), t23);
}

__device__ __forceinline__ void st4h(__half* p, float o0, float o1, float o2, float o3)
{
    __half2 lo = __floats2half2_rn(o0, o1);
    __half2 hi = __floats2half2_rn(o2, o3);
    uint2 v; v.x = *reinterpret_cast<unsigned*>(&lo); v.y = *reinterpret_cast<unsigned*>(&hi);
    *reinterpret_cast<uint2*>(p) = v;
}

// ---------------------------------------------------------------------------
// Kernel 1 (fused): Sobel edge -> (g_E, smem) -> hmax11 -> g_A
// Block = 8 rows x full width. Edge rows land in smem; hmax is row-local.
// ---------------------------------------------------------------------------
#define ET 8

__device__ __forceinline__ void load_row6(const float* p, int x0, float* r)
{
    r[0] = (x0 > 0) ? p[x0-1] : 0.f;
    float4 v = ld4f(p + x0); r[1]=v.x; r[2]=v.y; r[3]=v.z; r[4]=v.w;
    r[5] = (x0+4 < WW) ? p[x0+4] : 0.f;
}

__device__ __forceinline__ void zero_row6(float* r)
{
    #pragma unroll
    for (int i=0;i<6;i++) r[i]=0.f;
}

__global__ void __launch_bounds__(256) k_edgehmax(const float* __restrict__ t)
{
    __shared__ __align__(16) __half sed[ET][WW];

    int x0  = threadIdx.x << 2;
    int grp = blockIdx.x;
    int b   = grp / (HH/ET);
    int y0  = (grp % (HH/ET)) * ET;

    float g[ET][4];
    #pragma unroll
    for (int k=0;k<ET;k++){ g[k][0]=0.f; g[k][1]=0.f; g[k][2]=0.f; g[k][3]=0.f; }

    #pragma unroll
    for (int c = 0; c < 3; c++) {
        const float* p = t + (size_t)b*3*PLANE + (size_t)c*PLANE;
        float row[3][6];
        if (y0 > 0) load_row6(p + (size_t)(y0-1)*WW, x0, row[0]);
        else        zero_row6(row[0]);
        load_row6(p + (size_t)y0*WW, x0, row[1]);

        #pragma unroll
        for (int k = 0; k < ET; k++) {
            int ynext = y0 + k + 1;
            float* nr = row[(k+2)%3];
            if (ynext <= HH-1) load_row6(p + (size_t)ynext*WW, x0, nr);
            else               zero_row6(nr);

            const float* a  = row[ k   %3];
            const float* bm = row[(k+1)%3];
            const float* cm = row[(k+2)%3];

            float s[6], d[6];
            #pragma unroll
            for (int i=0;i<6;i++){ s[i] = fmaf(2.f, bm[i], a[i]+cm[i]); d[i] = cm[i]-a[i]; }
            #pragma unroll
            for (int j=0;j<4;j++){
                float gx = s[j+2] - s[j];
                float gy = fmaf(2.f, d[j+1], d[j]+d[j+2]);
                g[k][j] = fmaxf(g[k][j], fabsf(gx) + fabsf(gy));
            }
        }
    }

    // write edge (half) to global + smem
    __half* obase = g_E + (size_t)b*PLANE + x0;
    #pragma unroll
    for (int k=0;k<ET;k++){
        float e0 = fminf(g[k][0]*2.f,1.f), e1 = fminf(g[k][1]*2.f,1.f);
        float e2 = fminf(g[k][2]*2.f,1.f), e3 = fminf(g[k][3]*2.f,1.f);
        __half2 lo = __floats2half2_rn(e0, e1);
        __half2 hi = __floats2half2_rn(e2, e3);
        uint2 v; v.x = *reinterpret_cast<unsigned*>(&lo); v.y = *reinterpret_cast<unsigned*>(&hi);
        *reinterpret_cast<uint2*>(obase + (size_t)(y0+k)*WW) = v;
        *reinterpret_cast<uint2*>(&sed[k][x0]) = v;
    }
    __syncthreads();

    // hmax11 from smem rows -> g_A
    __half* hbase = g_A + (size_t)b*PLANE + x0;
    #pragma unroll
    for (int k=0;k<ET;k++){
        float a[14], o[4];
        hwin14(&sed[k][0], x0, a);
        htree11<true>(a, o);
        st4h(hbase + (size_t)(y0+k)*WW, o[0], o[1], o[2], o[3]);
    }
}

// ---------------------------------------------------------------------------
// Kernel 2 (fused): vmax11 (batch MLP=18 tree) -> smem -> hmin11 -> g_B2
// Dilated intermediate never touches global memory.
// ---------------------------------------------------------------------------
struct H4 { __half2 x, y; };

__device__ __forceinline__ H4 ldh4(const __half* p)
{
    uint2 v = *reinterpret_cast<const uint2*>(p);
    H4 r;
    r.x = *reinterpret_cast<__half2*>(&v.x);
    r.y = *reinterpret_cast<__half2*>(&v.y);
    return r;
}

template<bool M>
__device__ __forceinline__ H4 roph4(H4 a, H4 b)
{
    H4 r;
    if (M) { r.x = __hmax2(a.x, b.x); r.y = __hmax2(a.y, b.y); }
    else   { r.x = __hmin2(a.x, b.x); r.y = __hmin2(a.y, b.y); }
    return r;
}

__global__ void __launch_bounds__(256) k_vmaxhmin()
{
    __shared__ __align__(16) __half sdm[8][WW];

    int t   = threadIdx.x;
    int x0  = t << 2;                  // 256 threads x 4 cols = full row
    int grp = blockIdx.x;
    int b   = grp >> 7;                // 128 groups per batch
    int y0  = (grp & 127) << 3;        // 8 rows per group
    const __half* base = g_A + (size_t)b*PLANE + x0;

    // vmax11: 18 batched loads, log-tree
    H4 a[18];
    #pragma unroll
    for (int i = 0; i < 18; i++) {
        int yy = y0 - 5 + i; yy = yy < 0 ? 0 : (yy > HH-1 ? HH-1 : yy);
        a[i] = ldh4(base + (size_t)yy*WW);
    }
    H4 m2[16], m4[12], m8[8];
    #pragma unroll
    for (int i = 0; i < 16; i++) m2[i] = roph4<true>(a[i],  a[i+1]);
    #pragma unroll
    for (int i = 0; i < 12; i++) m4[i] = roph4<true>(m2[i], m2[i+2]);
    #pragma unroll
    for (int i = 0; i <  8; i++) m8[i] = roph4<true>(m4[i], m4[i+4]);

    #pragma unroll
    for (int j = 0; j < 8; j++) {
        H4 o = roph4<true>(m8[j], roph4<true>(m2[j+8], a[j+10]));
        uint2 v;
        v.x = *reinterpret_cast<unsigned*>(&o.x);
        v.y = *reinterpret_cast<unsigned*>(&o.y);
        *reinterpret_cast<uint2*>(&sdm[j][x0]) = v;
    }
    __syncthreads();

    // hmin11 from smem rows -> g_B2
    __half* obase = g_B2 + (size_t)b*PLANE + x0;
    #pragma unroll
    for (int j = 0; j < 8; j++) {
        float w[14], o[4];
        hwin14(&sdm[j][0], x0, w);
        htree11<false>(w, o);
        st4h(obase + (size_t)(y0+j)*WW, o[0], o[1], o[2], o[3]);
    }
}

// ---------------------------------------------------------------------------
// Kernel 3: vmin11 (batch tree) : g_B2 -> g_A (closed)
// ---------------------------------------------------------------------------
__global__ void __launch_bounds__(256) k_vmin11()
{
    int t   = threadIdx.x;
    int x0  = t << 2;
    int grp = blockIdx.x;
    int b   = grp >> 7;
    int y0  = (grp & 127) << 3;
    const __half* base  = g_B2 + (size_t)b*PLANE + x0;
    __half*       obase = g_A  + (size_t)b*PLANE + x0;

    H4 a[18];
    #pragma unroll
    for (int i = 0; i < 18; i++) {
        int yy = y0 - 5 + i; yy = yy < 0 ? 0 : (yy > HH-1 ? HH-1 : yy);
        a[i] = ldh4(base + (size_t)yy*WW);
    }
    H4 m2[16], m4[12], m8[8];
    #pragma unroll
    for (int i = 0; i < 16; i++) m2[i] = roph4<false>(a[i],  a[i+1]);
    #pragma unroll
    for (int i = 0; i < 12; i++) m4[i] = roph4<false>(m2[i], m2[i+2]);
    #pragma unroll
    for (int i = 0; i <  8; i++) m8[i] = roph4<false>(m4[i], m4[i+4]);

    #pragma unroll
    for (int j = 0; j < 8; j++) {
        H4 o = roph4<false>(m8[j], roph4<false>(m2[j+8], a[j+10]));
        uint2 v;
        v.x = *reinterpret_cast<unsigned*>(&o.x);
        v.y = *reinterpret_cast<unsigned*>(&o.y);
        *reinterpret_cast<uint2*>(obase + (size_t)(y0+j)*WW) = v;
    }
}

// ---------------------------------------------------------------------------
// Kernel 4: mask = relu(closed-edge) -> 5x5 max -> masked OKLab loss.
// closed in g_A, edge in g_E. 4 cols/thread, float4 ring of 5, MT=16.
// ---------------------------------------------------------------------------
__device__ __forceinline__ float4 maskrow_h5(const __half* __restrict__ pc,
                                             const __half* __restrict__ pe, int x0)
{
    float m[8];   // positions x0-2 .. x0+5
    if (x0 >= 4 && x0 <= WW-8) {
        uint2 C0 = *reinterpret_cast<const uint2*>(pc + x0 - 4);
        uint2 C1 = *reinterpret_cast<const uint2*>(pc + x0);
        uint2 C2 = *reinterpret_cast<const uint2*>(pc + x0 + 4);
        uint2 E0 = *reinterpret_cast<const uint2*>(pe + x0 - 4);
        uint2 E1 = *reinterpret_cast<const uint2*>(pe + x0);
        uint2 E2 = *reinterpret_cast<const uint2*>(pe + x0 + 4);
        float2 c, e;
        c = h2f(C0.y); e = h2f(E0.y);
        m[0] = fmaxf(c.x - e.x, 0.f); m[1] = fmaxf(c.y - e.y, 0.f);
        c = h2f(C1.x); e = h2f(E1.x);
        m[2] = fmaxf(c.x - e.x, 0.f); m[3] = fmaxf(c.y - e.y, 0.f);
        c = h2f(C1.y); e = h2f(E1.y);
        m[4] = fmaxf(c.x - e.x, 0.f); m[5] = fmaxf(c.y - e.y, 0.f);
        c = h2f(C2.x); e = h2f(E2.x);
        m[6] = fmaxf(c.x - e.x, 0.f); m[7] = fmaxf(c.y - e.y, 0.f);
    } else {
        #pragma unroll
        for (int i=0;i<8;i++){
            int xx = x0-2+i; xx = xx < 0 ? 0 : (xx > WW-1 ? WW-1 : xx);
            m[i] = fmaxf(__half2float(pc[xx]) - __half2float(pe[xx]), 0.f);
        }
    }
    float C   = fmaxf(m[3], m[4]);
    float t12 = fmaxf(m[1], m[2]);
    float t56 = fmaxf(m[5], m[6]);
    float4 o;
    o.x = fmaxf(C, fmaxf(m[0], t12));
    o.y = fmaxf(C, fmaxf(t12,  m[5]));
    o.z = fmaxf(fmaxf(C, m[2]), t56);
    o.w = fmaxf(fmaxf(C, m[7]), t56);
    return o;
}

__device__ __forceinline__ float s2l(float x)
{
    x = fminf(fmaxf(x, 0.f), 1.f);
    return (x <= 0.04045f) ? x * (1.f/12.92f)
                           : __powf((x + 0.055f) * (1.f/1.055f), 2.4f);
}

__device__ __forceinline__ void oklab_ab(float r, float g, float bl, float& A, float& Bc)
{
    float lr = s2l(r), lg = s2l(g), lb = s2l(bl);
    float l = 0.4122214708f*lr + 0.5363325363f*lg + 0.0514459929f*lb;
    float m = 0.2119034982f*lr + 0.6806995451f*lg + 0.1073969566f*lb;
    float s = 0.0883024619f*lr + 0.2817188376f*lg + 0.6299787005f*lb;
    l = cbrtf(fmaxf(l, 1e-10f));
    m = cbrtf(fmaxf(m, 1e-10f));
    s = cbrtf(fmaxf(s, 1e-10f));
    A  = 1.9779984951f*l - 2.428592205f*m + 0.4505937099f*s;
    Bc = 0.0259040371f*l + 0.7827717662f*m - 0.808675766f*s;
}

#define MT 16

__global__ void __launch_bounds__(256) k_maskloss(const float* __restrict__ pred,
                                                  const float* __restrict__ tgt)
{
    int x0   = threadIdx.x << 2;
    int grp  = blockIdx.x;
    int b    = grp / (HH/MT);
    int y0   = (grp % (HH/MT)) * MT;
    const __half* cb = g_A + (size_t)b*PLANE;   // closed
    const __half* eb = g_E + (size_t)b*PLANE;   // edge

    float msum = 0.f, chroma = 0.f, hue = 0.f;

    float4 r[5];
    #pragma unroll
    for (int i = 0; i < 4; i++) {
        int yy = y0 - 2 + i; yy = yy < 0 ? 0 : yy;
        r[i] = maskrow_h5(cb + (size_t)yy*WW, eb + (size_t)yy*WW, x0);
    }
    #pragma unroll
    for (int k = 0; k < MT; k++) {
        int yy = y0 + k + 2; yy = yy > HH-1 ? HH-1 : yy;
        r[(4+k) % 5] = maskrow_h5(cb + (size_t)yy*WW, eb + (size_t)yy*WW, x0);
        float4 o = r[0];
        #pragma unroll
        for (int i=1;i<5;i++){
            o.x = fmaxf(o.x, r[i].x); o.y = fmaxf(o.y, r[i].y);
            o.z = fmaxf(o.z, r[i].z); o.w = fmaxf(o.w, r[i].w);
        }
        msum += (o.x + o.y) + (o.z + o.w);
        if (o.x > 0.f || o.y > 0.f || o.z > 0.f || o.w > 0.f) {
            size_t base = (size_t)b*3*PLANE + (size_t)(y0+k)*WW + x0;
            float mv[4] = {o.x, o.y, o.z, o.w};
            #pragma unroll 1
            for (int j = 0; j < 4; j++) {
                float m = mv[j];
                if (m > 0.f) {
                    float pa,pb,ta,tb;
                    oklab_ab(pred[base+j], pred[base+j+PLANE], pred[base+j+2*PLANE], pa, pb);
                    oklab_ab(tgt [base+j], tgt [base+j+PLANE], tgt [base+j+2*PLANE], ta, tb);
                    float Cp = sqrtf(fmaf(pa,pa, pb*pb) + 1e-12f);
                    float Cg = sqrtf(fmaf(ta,ta, tb*tb) + 1e-12f);
                    chroma += fabsf(Cp - Cg) * m;
                    float cosd = (pa*ta + pb*tb) / (Cp*Cg + 1e-12f);
                    cosd = fminf(fmaxf(cosd, -1.f), 1.f);
                    hue += fmaxf(Cg, 0.01f) * (1.f - cosd) * m;
                }
            }
        }
    }

    #pragma unroll
    for (int o2=16; o2; o2>>=1){
        msum   += __shfl_xor_sync(0xffffffffu, msum,   o2);
        chroma += __shfl_xor_sync(0xffffffffu, chroma, o2);
        hue    += __shfl_xor_sync(0xffffffffu, hue,    o2);
    }
    __shared__ float sm[3][8];
    int w = threadIdx.x >> 5, lane = threadIdx.x & 31;
    if (lane == 0){ sm[0][w]=msum; sm[1][w]=chroma; sm[2][w]=hue; }
    __syncthreads();
    if (threadIdx.x == 0){
        float a=0.f, c=0.f, h=0.f;
        #pragma unroll
        for (int i=0;i<8;i++){ a+=sm[0][i]; c+=sm[1][i]; h+=sm[2][i]; }
        atomicAdd(&g_acc[0], a);
        atomicAdd(&g_acc[1], c);
        atomicAdd(&g_acc[2], h);
    }
}

__global__ void k_zero(){ if (threadIdx.x < 3) g_acc[threadIdx.x] = 0.f; }

__global__ void k_fin(float* out)
{
    float ms = fmaxf(g_acc[0], 1.f);
    out[0] = g_acc[1]/ms + 2.f*(g_acc[2]/ms);
}

// ---------------------------------------------------------------------------
extern "C" void kernel_launch(void* const* d_in, const int* in_sizes, int n_in,
                              void* d_out, int out_size)
{
    const float* pred = (const float*)d_in[0];
    const float* tgt  = (const float*)d_in[1];
    float* out = (float*)d_out;

    const int egrid = BBATCH*HH/ET;        // 1024
    const int vgrid = BBATCH*(HH/8);       // 1024
    const int mgrid = BBATCH*HH/MT;        // 512
    dim3 blk(256);

    k_zero     <<<1, 32>>>();
    k_edgehmax <<<egrid, blk>>>(tgt);       // tgt -> g_E (edge) + g_A (hmax)
    k_vmaxhmin <<<vgrid, blk>>>();          // g_A -> g_B2 (hmin of dilated)
    k_vmin11   <<<vgrid, blk>>>();          // g_B2 -> g_A (closed)
    k_maskloss <<<mgrid, blk>>>(pred, tgt); // (g_A, g_E, pred, tgt) -> g_acc
    k_fin      <<<1, 1>>>(out);
}